// round 6
// baseline (speedup 1.0000x reference)
#include <cuda_runtime.h>
#include <cstddef>
#include <cstdint>
#include <math.h>

// CTC batch cost (Keras semantics): B=256, T=512, V=256, L=64, blank=V-1
// loss[b] = -log P(y_true[b] | y_pred[b]), logp = log(y_pred + 1e-7)
//
// Warp-specialized producer/consumer, one 128-thread block per batch element.
//   warp 0           : serial CTC DP (linear domain, per-lane pow2 scaling)
//   warps 1-2 (p=0..63): label-column producers, 32 cp.async / superstep
//   warp 3 (k=0..31) : blank-column producer, thread k owns timestep k,
//                      1 cp.async / superstep (R4 redundantly loaded blank
//                      32x per timestep)
// 4-slot smem ring, issue-ahead 2, ONE __syncthreads per superstep (slot
// distance analysis makes the trailing barrier of R4 redundant).
//
// DP (warp 0), lane j owns states:
//   La=alpha[label 2j], Lb=alpha[label 2j+1], Ba=alpha[blank 2j],
//   Bb=alpha[blank 2j+1], B64=alpha[blank 64] (lane31).
// Recurrence (p' = p + eps), tp = (lane j-1's Lb) * corr:
//   nLa=(La+Ba+sa*tp)*p'[lab2j]   nLb=(Lb+Bb+sb*La)*p'[lab2j+1]
//   nBa=(Ba+tp)*p'[blank]         nBb=(Bb+La)*p'[blank]
//   nB64=(B64+Lb)*p'[blank]
// Per-lane power-of-2 renorm every 8 steps (exact integer exponents) keeps
// every lineage representable in fp32 (rel_err 3.9e-7 in R2-R4).

#define B_   256
#define T_   512
#define V_   256
#define L_   64
#define GT   32            // timesteps per superstep
#define NG   (T_ / GT)     // 16 supersteps
#define NVP  66            // row: 64 label cols + blank (idx 64) + pad
#define NSL  4             // ring slots
#define EPS  1e-7f
#define FULL 0xFFFFFFFFu
#define MAXGAP 64
#define LN2F 0.6931471805599453f

__device__ __forceinline__ float exp2i(int e)
{
    if (e <= -127) return 0.0f;
    if (e > 127)   e = 127;
    return __int_as_float((e + 127) << 23);
}

__device__ __forceinline__ void cp_async4(uint32_t saddr, const float* gaddr)
{
    asm volatile("cp.async.ca.shared.global [%0], [%1], 4;\n"
                 :: "r"(saddr), "l"(gaddr) : "memory");
}

__global__ void __launch_bounds__(128, 2)
ctc_forward_kernel(const int* __restrict__ y_true,
                   const float* __restrict__ y_pred,
                   float* __restrict__ out)
{
    __shared__ float buf[NSL][GT][NVP];   // 4*32*66*4 = 33792 B ring
    __shared__ int   lab_s[L_];

    const int b    = blockIdx.x;
    const int tid  = threadIdx.x;
    const int lane = tid & 31;

    const float* base = y_pred + (size_t)b * (size_t)(T_ * V_);

    if (tid < L_) lab_s[tid] = y_true[b * L_ + tid];
    __syncthreads();

    // ---------------- producer setup ----------------
    const bool lab_prod = (tid >= 32 && tid < 96);   // warps 1-2
    const bool blk_prod = (tid >= 96);               // warp 3
    int col = 0;
    uint32_t sp0 = 0;   // smem target in slot 0
    if (lab_prod) {
        const int p = tid - 32;                      // 0..63 -> label column p
        col = lab_s[p];
        sp0 = (uint32_t)__cvta_generic_to_shared(&buf[0][0][p]);
    } else if (blk_prod) {
        // thread k handles blank for timestep k of each superstep
        const int k = tid - 96;                      // 0..31
        col = V_ - 1;
        sp0 = (uint32_t)__cvta_generic_to_shared(&buf[0][k][64]);
    }

    // Label producers: 32 loads (one per timestep). Blank producers: 1 load.
#define ISSUE_GROUP(g)                                                     \
    do {                                                                   \
        uint32_t _sp = sp0 + (uint32_t)(((g) & (NSL - 1)) * GT * NVP * 4); \
        if (lab_prod) {                                                    \
            const float* _gp = base + (size_t)(g) * GT * V_ + col;         \
            _Pragma("unroll")                                              \
            for (int _k = 0; _k < GT; ++_k)                                \
                cp_async4(_sp + _k * NVP * 4, _gp + (size_t)_k * V_);      \
        } else {                                                           \
            const float* _gp = base                                        \
                + (size_t)((g) * GT + (tid - 96)) * V_ + col;              \
            cp_async4(_sp, _gp);                                           \
        }                                                                  \
        asm volatile("cp.async.commit_group;\n" ::: "memory");             \
    } while (0)

    // ---------------- consumer setup (warp 0) ----------------
    float sa = 0.0f, sb = 0.0f;
    if (tid < 32) {
        int la = lab_s[2 * lane];
        int lb = lab_s[2 * lane + 1];
        int lprev = __shfl_up_sync(FULL, lb, 1);
        sa = (la != lprev) ? 1.0f : 0.0f;   // lane0 irrelevant (tp=0)
        sb = (lb != la) ? 1.0f : 0.0f;
    }

    float La = 0.0f, Lb_s = 0.0f, Ba = (lane == 0) ? 1.0f : 0.0f, Bb = 0.0f, B64 = 0.0f;
    int   off  = 0;
    float corr = (lane == 0) ? 0.0f : 1.0f;

#define STEP(pa_, pb_, pq_)                                         \
    do {                                                            \
        float _pa = (pa_) + EPS;                                    \
        float _pb = (pb_) + EPS;                                    \
        float _pq = (pq_) + EPS;                                    \
        float _tp = __shfl_up_sync(FULL, Lb_s, 1) * corr;           \
        float _nLa = (La + Ba + sa * _tp) * _pa;                    \
        float _nLb = (Lb_s + Bb + sb * La) * _pb;                   \
        float _nBa = (Ba + _tp) * _pq;                              \
        float _nBb = (Bb + La) * _pq;                               \
        float _nB6 = (B64 + Lb_s) * _pq;                            \
        La = _nLa; Lb_s = _nLb; Ba = _nBa; Bb = _nBb; B64 = _nB6;   \
    } while (0)

#define RENORM()                                                            \
    do {                                                                    \
        float _m = fmaxf(fmaxf(fmaxf(La, Lb_s), fmaxf(Ba, Bb)), B64);       \
        bool _dead = (_m <= 0.0f);                                          \
        int _iexp = _dead ? 0 : (((__float_as_int(_m) >> 23) & 255) - 127); \
        if (_iexp < -120) _iexp = -120;                                     \
        int _offnew = off + _iexp;                                          \
        int _up = __shfl_up_sync(FULL, _offnew, 1);                         \
        int _offfin;                                                        \
        if (lane == 0)      _offfin = _offnew;                              \
        else if (_dead)     _offfin = _up;                                  \
        else                _offfin = (_up - MAXGAP > _offnew)              \
                                        ? (_up - MAXGAP) : _offnew;         \
        if (!_dead) {                                                       \
            float _f = exp2i(off - _offfin);                                \
            La *= _f; Lb_s *= _f; Ba *= _f; Bb *= _f; B64 *= _f;            \
        }                                                                   \
        off = _offfin;                                                      \
        int _upf = __shfl_up_sync(FULL, _offfin, 1);                        \
        int _dd = _upf - _offfin;                                           \
        if (_dd > 100) _dd = 100;                                           \
        corr = (lane == 0) ? 0.0f : exp2i(_dd);                             \
    } while (0)

    // Prologue: issue-ahead 2
    if (tid >= 32) {
        ISSUE_GROUP(0);
        ISSUE_GROUP(1);
    }

    // Main loop. Per superstep g:
    //   producers: issue g+2 (slot (g+2)%4), then wait until group g landed
    //   barrier
    //   consumer: read slot g%4
    // Slot safety: writer slots (g+1)%4,(g+2)%4 never equal reader slots
    // (g-1)%4 or g%4; slot reuse g+4 is ordered by barrier g+2 > consumer's
    // completion of g (consumer reaches barrier g+1 only after reading g).
    for (int g = 0; g < NG; ++g) {
        if (tid >= 32) {
            if (g + 2 < NG) {
                ISSUE_GROUP(g + 2);
                asm volatile("cp.async.wait_group 2;\n" ::: "memory");
            } else if (g + 1 < NG) {
                asm volatile("cp.async.wait_group 1;\n" ::: "memory");
            } else {
                asm volatile("cp.async.wait_group 0;\n" ::: "memory");
            }
        }
        __syncthreads();
        if (tid < 32) {
            const float (*slab)[NVP] = buf[g & (NSL - 1)];
#pragma unroll
            for (int k = 0; k < GT; ++k) {
                STEP(slab[k][2 * lane], slab[k][2 * lane + 1], slab[k][64]);
                if ((k & 7) == 7) RENORM();
            }
        }
    }

    // final: alpha[S-1] = blank[64] (lane31 B64), alpha[S-2] = label[63] (lane31 Lb)
    if (tid < 32 && lane == 31) {
        float v = B64 + Lb_s;                      // scaled by 2^off
        out[b] = -((__log2f(v) + (float)off) * LN2F);
    }
}

extern "C" void kernel_launch(void* const* d_in, const int* in_sizes, int n_in,
                              void* d_out, int out_size)
{
    // Identify inputs by element count: y_true is B*L int32, y_pred is B*T*V f32
    const int* y_true = nullptr;
    const float* y_pred = nullptr;
    if (in_sizes[0] == B_ * L_) {
        y_true = (const int*)d_in[0];
        y_pred = (const float*)d_in[1];
    } else {
        y_true = (const int*)d_in[1];
        y_pred = (const float*)d_in[0];
    }
    float* out = (float*)d_out;

    // One block per batch element
    ctc_forward_kernel<<<B_, 128>>>(y_true, y_pred, out);
}

// round 7
// speedup vs baseline: 1.1998x; 1.1998x over previous
#include <cuda_runtime.h>
#include <cstddef>
#include <cstdint>
#include <math.h>

// CTC batch cost (Keras semantics): B=256, T=512, V=256, L=64, blank=V-1
// loss[b] = -log P(y_true[b] | y_pred[b]), logp = log(y_pred + 1e-7)
//
// R7 design: R3's barrier-free register-pipelined DP warp (proven 37.6us,
// rel_err 3.9e-7) + 3 sync-free L2-PREFETCH warps per block.
//   - R3's limiter was the per-warp outstanding-LDG cap (~55): one DP warp
//     per element can't keep enough bytes in flight -> DRAM stuck at 47%.
//   - R6's barrier-coupled producer/consumer regressed (45us, issue 8.9%):
//     the serial DP chain must not be coupled to memory waits.
//   - Now: loader warps stream FULL rows into L2 (one ld.global.cg per lane
//     = 32 sectors = whole 1KB row per warp instruction; the gather needs
//     ~29/32 sectors anyway so full-row fetch costs only +10% traffic).
//     No synchronization: if a row hasn't landed, the DP warp's own load
//     just goes to DRAM (correct, merely slower). DP gathers then hit L2
//     (~250cyc), fully covered by its 55-load cap and depth-3 pipeline.
//   - DP warp rotated across SMSPs: dpw=(bid>>2)&3 (bid and bid+148 are
//     co-resident; 148%4==0 so bid&3 would stack both DP warps on SMSP0).
//
// DP (1 warp), lane j owns states:
//   La=alpha[label 2j], Lb=alpha[label 2j+1], Ba=alpha[blank 2j],
//   Bb=alpha[blank 2j+1], B64=alpha[blank 64] (lane31).
// Linear-domain recurrence, per-lane power-of-2 scaling, renorm every 8
// steps with exact integer exponent bookkeeping (identical math to R3).

#define B_  256
#define T_  512
#define V_  256
#define L_  64
#define CH  8
#define NCH (T_ / CH)
#define EPS 1e-7f
#define FULL 0xFFFFFFFFu
#define MAXGAP 64
#define LN2F 0.6931471805599453f

__device__ __forceinline__ float exp2i(int e)
{
    if (e <= -127) return 0.0f;
    if (e > 127)   e = 127;
    return __int_as_float((e + 127) << 23);
}

__global__ void __launch_bounds__(128)
ctc_forward_kernel(const int* __restrict__ y_true,
                   const float* __restrict__ y_pred,
                   float* __restrict__ out)
{
    const int b    = blockIdx.x;           // one batch element per block
    const int tid  = threadIdx.x;
    const int wid  = tid >> 5;
    const int lane = tid & 31;
    const int dpw  = (b >> 2) & 3;         // rotated DP-warp slot

    const float* base = y_pred + (size_t)b * (size_t)(T_ * V_);

    if (wid != dpw) {
        // ---------- L2 prefetch warp (sync-free) ----------
        // rank 0..2; covers rows r = rank, rank+3, ... Each warp instruction
        // touches all 32 sectors of one 1KB row (lane -> sector).
        const int rank = ((wid - dpw) & 3) - 1;
        const char* ap = (const char*)base
                       + (size_t)rank * (V_ * 4) + (size_t)lane * 32;
#pragma unroll 4
        for (int r = rank; r < T_; r += 3) {
            unsigned v;
            asm volatile("ld.global.cg.b32 %0, [%1];"
                         : "=r"(v) : "l"(ap) : "memory");
            ap += 3 * V_ * 4;
        }
        return;
    }

    // ---------------- DP warp (identical math to R3) ----------------
    const int* lrow = y_true + b * L_;
    const int la = lrow[2 * lane];
    const int lb = lrow[2 * lane + 1];
    const int lprev = __shfl_up_sync(FULL, lb, 1);  // label[2j-1]; lane0 unused
    const float sa = (la != lprev) ? 1.0f : 0.0f;   // lane0 irrelevant (tp=0)
    const float sb = (lb != la) ? 1.0f : 0.0f;

    float La = 0.0f, Lb_s = 0.0f, Ba = (lane == 0) ? 1.0f : 0.0f, Bb = 0.0f, B64 = 0.0f;
    int   off  = 0;                               // lane's log2 scale offset
    float corr = (lane == 0) ? 0.0f : 1.0f;       // 2^(off[j-1]-off[j])

    // 4 rotating prefetch buffers (depth-3 pipeline)
    float P0a[CH], P0b[CH], P0q[CH];
    float P1a[CH], P1b[CH], P1q[CH];
    float P2a[CH], P2b[CH], P2q[CH];
    float P3a[CH], P3b[CH], P3q[CH];

#define LOAD_CHUNK(pa, pb, pq, t0)                                  \
    do {                                                            \
        const float* _r = base + (size_t)(t0) * V_;                 \
        _Pragma("unroll")                                           \
        for (int _i = 0; _i < CH; ++_i) {                           \
            pa[_i] = __ldcs(_r + (size_t)_i * V_ + la);             \
            pb[_i] = __ldcs(_r + (size_t)_i * V_ + lb);             \
            pq[_i] = __ldcs(_r + (size_t)_i * V_ + (V_ - 1));       \
        }                                                           \
    } while (0)

#define STEP(pa_, pb_, pq_)                                         \
    do {                                                            \
        float _pa = (pa_) + EPS;                                    \
        float _pb = (pb_) + EPS;                                    \
        float _pq = (pq_) + EPS;                                    \
        float _tp = __shfl_up_sync(FULL, Lb_s, 1) * corr;           \
        float _nLa = (La + Ba + sa * _tp) * _pa;                    \
        float _nLb = (Lb_s + Bb + sb * La) * _pb;                   \
        float _nBa = (Ba + _tp) * _pq;                              \
        float _nBb = (Bb + La) * _pq;                               \
        float _nB6 = (B64 + Lb_s) * _pq;                            \
        La = _nLa; Lb_s = _nLb; Ba = _nBa; Bb = _nBb; B64 = _nB6;   \
    } while (0)

#define RENORM()                                                            \
    do {                                                                    \
        float _m = fmaxf(fmaxf(fmaxf(La, Lb_s), fmaxf(Ba, Bb)), B64);       \
        bool _dead = (_m <= 0.0f);                                          \
        int _iexp = _dead ? 0 : (((__float_as_int(_m) >> 23) & 255) - 127); \
        if (_iexp < -120) _iexp = -120;                                     \
        int _offnew = off + _iexp;                                          \
        int _up = __shfl_up_sync(FULL, _offnew, 1);                         \
        int _offfin;                                                        \
        if (lane == 0)      _offfin = _offnew;                              \
        else if (_dead)     _offfin = _up;     /* adopt upstream scale */   \
        else                _offfin = (_up - MAXGAP > _offnew)              \
                                        ? (_up - MAXGAP) : _offnew;         \
        if (!_dead) {                                                       \
            float _f = exp2i(off - _offfin);                                \
            La *= _f; Lb_s *= _f; Ba *= _f; Bb *= _f; B64 *= _f;            \
        }                                                                   \
        off = _offfin;                                                      \
        int _upf = __shfl_up_sync(FULL, _offfin, 1);                        \
        int _dd = _upf - _offfin;                                           \
        if (_dd > 100) _dd = 100;                                           \
        corr = (lane == 0) ? 0.0f : exp2i(_dd);                             \
    } while (0)

#define PROC(pa, pb, pq)                                              \
    do {                                                              \
        _Pragma("unroll")                                             \
        for (int _s = 0; _s < CH; ++_s) STEP(pa[_s], pb[_s], pq[_s]); \
        RENORM();                                                     \
    } while (0)

    // Prime the pipeline: 3 chunks in flight
    LOAD_CHUNK(P0a, P0b, P0q, 0 * CH);
    LOAD_CHUNK(P1a, P1b, P1q, 1 * CH);
    LOAD_CHUNK(P2a, P2b, P2q, 2 * CH);

    for (int c = 0; c < NCH; c += 4) {
        if (c + 3 < NCH) LOAD_CHUNK(P3a, P3b, P3q, (c + 3) * CH);
        PROC(P0a, P0b, P0q);

        if (c + 4 < NCH) LOAD_CHUNK(P0a, P0b, P0q, (c + 4) * CH);
        PROC(P1a, P1b, P1q);

        if (c + 5 < NCH) LOAD_CHUNK(P1a, P1b, P1q, (c + 5) * CH);
        PROC(P2a, P2b, P2q);

        if (c + 6 < NCH) LOAD_CHUNK(P2a, P2b, P2q, (c + 6) * CH);
        PROC(P3a, P3b, P3q);
    }

    // final: alpha[S-1] = blank[64] (lane31 B64), alpha[S-2] = label[63] (lane31 Lb)
    if (lane == 31) {
        float v = B64 + Lb_s;                      // scaled by 2^off
        out[b] = -((__log2f(v) + (float)off) * LN2F);
    }
}

extern "C" void kernel_launch(void* const* d_in, const int* in_sizes, int n_in,
                              void* d_out, int out_size)
{
    // Identify inputs by element count: y_true is B*L int32, y_pred is B*T*V f32
    const int* y_true = nullptr;
    const float* y_pred = nullptr;
    if (in_sizes[0] == B_ * L_) {
        y_true = (const int*)d_in[0];
        y_pred = (const float*)d_in[1];
    } else {
        y_true = (const int*)d_in[1];
        y_pred = (const float*)d_in[0];
    }
    float* out = (float*)d_out;

    // One 128-thread block per batch element:
    //   1 DP warp (rotated slot) + 3 L2-prefetch warps, zero synchronization
    ctc_forward_kernel<<<B_, 128>>>(y_true, y_pred, out);
}

// round 8
// speedup vs baseline: 1.5337x; 1.2783x over previous
#include <cuda_runtime.h>
#include <cstddef>
#include <cstdint>
#include <math.h>

// CTC batch cost (Keras semantics): B=256, T=512, V=256, L=64, blank=V-1
// loss[b] = -log P(y_true[b] | y_pred[b]), logp = log(y_pred + 1e-7)
//
// R8: MEET-IN-THE-MIDDLE bidirectional DP. R3/R7 pinned the limiter as
// per-warp serial cost (outstanding-LDG cap ~55 + serial chain): helper
// prefetch warps were exactly neutral. The only lever is more DP warps per
// element. CTC splits exactly: P = sum_s alpha_{255}(s) * B_{256}(s),
//   warp 0: forward alpha over t=0..255   (R3 recurrence, unchanged)
//   warp 1: backward beta~ over t=511..256 (mirrored recurrence)
// then one __syncthreads + log2-domain dot over the 129 states.
// Halves serial chain AND per-warp loads; doubles warps chip-wide.
//
// Lane j owns states (both warps, same layout):
//   Ba=s4j(blank), La=s4j+1(lab2j), Bb=s4j+2(blank), Lb=s4j+3(lab2j+1),
//   lane31 extra B64=s128(blank).
// Forward step (p'=p+eps), tp = prev-lane Lb * corr:
//   Ba'=(Ba+tp)pq  La'=(La+Ba+sa*tp)pa  Bb'=(Bb+La)pq
//   Lb'=(Lb+Bb+sb*La)pb  B64'=(B64+Lb)pq
// Backward step (skip into blanks is always 0), nb/nl = next-lane Ba/La:
//   Ba'=(Ba+La)pq  La'=(La+Bb+sb*Lb)pa  Bb'=(Bb+Lb)pq
//   Lb'=(Lb+nb+saN*nl)pb  B64'=B64*pq      [lane31: nb=B64, nl=0]
// Backward init: zeros, lane31 B64=1  (encodes B_T(s)=1 for s>=127).
// Per-lane power-of-2 scaling, renorm every 8 steps, exact integer exps.

#define B_  256
#define T_  512
#define V_  256
#define L_  64
#define CH  8
#define HT  (T_ / 2)        // 256 steps per direction
#define NCH (HT / CH)       // 32 chunks per direction
#define EPS 1e-7f
#define FULL 0xFFFFFFFFu
#define MAXGAP 64
#define LN2F 0.6931471805599453f

__device__ __forceinline__ float exp2i(int e)
{
    if (e <= -127) return 0.0f;
    if (e > 127)   e = 127;
    return __int_as_float((e + 127) << 23);
}

__global__ void __launch_bounds__(64)
ctc_forward_kernel(const int* __restrict__ y_true,
                   const float* __restrict__ y_pred,
                   float* __restrict__ out)
{
    __shared__ float sBv[32][5];   // backward B-values per lane
    __shared__ int   sBo[32];      // backward off per lane

    const int b    = blockIdx.x;
    const int wid  = threadIdx.x >> 5;
    const int lane = threadIdx.x & 31;

    const float* base = y_pred + (size_t)b * (size_t)(T_ * V_);
    const int* lrow = y_true + b * L_;
    const int la = lrow[2 * lane];
    const int lb = lrow[2 * lane + 1];
    const int lprev = __shfl_up_sync(FULL, lb, 1);    // label[2j-1]
    const int lnext = __shfl_down_sync(FULL, la, 1);  // label[2j+2]
    const float sa  = (la != lprev) ? 1.0f : 0.0f;    // lane0 irrelevant
    const float saN = (lnext != lb) ? 1.0f : 0.0f;    // lane31 irrelevant
    const float sb  = (lb != la) ? 1.0f : 0.0f;

    // DP state (meaning differs per warp), per-lane scale
    float Ba, La_v, Bb, Lb_v, B64;
    int   off  = 0;
    float corr;

    float P0a[CH], P0b[CH], P0q[CH];
    float P1a[CH], P1b[CH], P1q[CH];
    float P2a[CH], P2b[CH], P2q[CH];
    float P3a[CH], P3b[CH], P3q[CH];

#define LOAD_CHUNK_F(pa, pb, pq, c)                                 \
    do {                                                            \
        const float* _r = base + (size_t)(c) * (CH * V_);           \
        _Pragma("unroll")                                           \
        for (int _i = 0; _i < CH; ++_i) {                           \
            pa[_i] = __ldcs(_r + (size_t)_i * V_ + la);             \
            pb[_i] = __ldcs(_r + (size_t)_i * V_ + lb);             \
            pq[_i] = __ldcs(_r + (size_t)_i * V_ + (V_ - 1));       \
        }                                                           \
    } while (0)

#define LOAD_CHUNK_B(pa, pb, pq, c)                                 \
    do {                                                            \
        const float* _r = base + (size_t)(T_ - 1 - (c) * CH) * V_;  \
        _Pragma("unroll")                                           \
        for (int _i = 0; _i < CH; ++_i) {                           \
            pa[_i] = __ldcs(_r - (size_t)_i * V_ + la);             \
            pb[_i] = __ldcs(_r - (size_t)_i * V_ + lb);             \
            pq[_i] = __ldcs(_r - (size_t)_i * V_ + (V_ - 1));       \
        }                                                           \
    } while (0)

#define STEP_F(pa_, pb_, pq_)                                       \
    do {                                                            \
        float _pa = (pa_) + EPS;                                    \
        float _pb = (pb_) + EPS;                                    \
        float _pq = (pq_) + EPS;                                    \
        float _tp = __shfl_up_sync(FULL, Lb_v, 1) * corr;           \
        float _nLa = (La_v + Ba + sa * _tp) * _pa;                  \
        float _nLb = (Lb_v + Bb + sb * La_v) * _pb;                 \
        float _nBa = (Ba + _tp) * _pq;                              \
        float _nBb = (Bb + La_v) * _pq;                             \
        float _nB6 = (B64 + Lb_v) * _pq;                            \
        La_v = _nLa; Lb_v = _nLb; Ba = _nBa; Bb = _nBb; B64 = _nB6; \
    } while (0)

#define STEP_B(pa_, pb_, pq_)                                       \
    do {                                                            \
        float _pa = (pa_) + EPS;                                    \
        float _pb = (pb_) + EPS;                                    \
        float _pq = (pq_) + EPS;                                    \
        float _nb = __shfl_down_sync(FULL, Ba, 1);                  \
        float _nl = __shfl_down_sync(FULL, La_v, 1);                \
        _nb = (lane == 31) ? B64 : _nb * corr;                      \
        _nl = (lane == 31) ? 0.0f : _nl * corr;                     \
        float _nBa = (Ba + La_v) * _pq;                             \
        float _nLa = (La_v + Bb + sb * Lb_v) * _pa;                 \
        float _nBb = (Bb + Lb_v) * _pq;                             \
        float _nLb = (Lb_v + _nb + saN * _nl) * _pb;                \
        float _nB6 = B64 * _pq;                                     \
        La_v = _nLa; Lb_v = _nLb; Ba = _nBa; Bb = _nBb; B64 = _nB6; \
    } while (0)

    // Forward renorm: corr couples lane j-1 -> j (shfl.up)
#define RENORM_F()                                                          \
    do {                                                                    \
        float _m = fmaxf(fmaxf(fmaxf(La_v, Lb_v), fmaxf(Ba, Bb)), B64);     \
        bool _dead = (_m <= 0.0f);                                          \
        int _iexp = _dead ? 0 : (((__float_as_int(_m) >> 23) & 255) - 127); \
        if (_iexp < -120) _iexp = -120;                                     \
        int _offnew = off + _iexp;                                          \
        int _up = __shfl_up_sync(FULL, _offnew, 1);                         \
        int _offfin;                                                        \
        if (lane == 0)      _offfin = _offnew;                              \
        else if (_dead)     _offfin = _up;                                  \
        else                _offfin = (_up - MAXGAP > _offnew)              \
                                        ? (_up - MAXGAP) : _offnew;         \
        if (!_dead) {                                                       \
            float _f = exp2i(off - _offfin);                                \
            La_v *= _f; Lb_v *= _f; Ba *= _f; Bb *= _f; B64 *= _f;          \
        }                                                                   \
        off = _offfin;                                                      \
        int _upf = __shfl_up_sync(FULL, _offfin, 1);                        \
        int _dd = _upf - _offfin;                                           \
        if (_dd > 100) _dd = 100;                                           \
        corr = (lane == 0) ? 0.0f : exp2i(_dd);                             \
    } while (0)

    // Backward renorm: corr couples lane j+1 -> j (shfl.down)
#define RENORM_B()                                                          \
    do {                                                                    \
        float _m = fmaxf(fmaxf(fmaxf(La_v, Lb_v), fmaxf(Ba, Bb)), B64);     \
        bool _dead = (_m <= 0.0f);                                          \
        int _iexp = _dead ? 0 : (((__float_as_int(_m) >> 23) & 255) - 127); \
        if (_iexp < -120) _iexp = -120;                                     \
        int _offnew = off + _iexp;                                          \
        int _dn = __shfl_down_sync(FULL, _offnew, 1);                       \
        int _offfin;                                                        \
        if (lane == 31)     _offfin = _offnew;                              \
        else if (_dead)     _offfin = _dn;                                  \
        else                _offfin = (_dn - MAXGAP > _offnew)              \
                                        ? (_dn - MAXGAP) : _offnew;         \
        if (!_dead) {                                                       \
            float _f = exp2i(off - _offfin);                                \
            La_v *= _f; Lb_v *= _f; Ba *= _f; Bb *= _f; B64 *= _f;          \
        }                                                                   \
        off = _offfin;                                                      \
        int _dnf = __shfl_down_sync(FULL, _offfin, 1);                      \
        int _dd = _dnf - _offfin;                                           \
        if (_dd > 100) _dd = 100;                                           \
        corr = (lane == 31) ? 0.0f : exp2i(_dd);                            \
    } while (0)

#define PROC_F(pa, pb, pq)                                              \
    do {                                                                \
        _Pragma("unroll")                                               \
        for (int _s = 0; _s < CH; ++_s) STEP_F(pa[_s], pb[_s], pq[_s]); \
        RENORM_F();                                                     \
    } while (0)

#define PROC_B(pa, pb, pq)                                              \
    do {                                                                \
        _Pragma("unroll")                                               \
        for (int _s = 0; _s < CH; ++_s) STEP_B(pa[_s], pb[_s], pq[_s]); \
        RENORM_B();                                                     \
    } while (0)

    if (wid == 0) {
        // -------- forward: t = 0..255 --------
        Ba = (lane == 0) ? 1.0f : 0.0f;
        La_v = Lb_v = Bb = B64 = 0.0f;
        corr = (lane == 0) ? 0.0f : 1.0f;

        LOAD_CHUNK_F(P0a, P0b, P0q, 0);
        LOAD_CHUNK_F(P1a, P1b, P1q, 1);
        LOAD_CHUNK_F(P2a, P2b, P2q, 2);
        for (int c = 0; c < NCH; c += 4) {
            if (c + 3 < NCH) LOAD_CHUNK_F(P3a, P3b, P3q, c + 3);
            PROC_F(P0a, P0b, P0q);
            if (c + 4 < NCH) LOAD_CHUNK_F(P0a, P0b, P0q, c + 4);
            PROC_F(P1a, P1b, P1q);
            if (c + 5 < NCH) LOAD_CHUNK_F(P1a, P1b, P1q, c + 5);
            PROC_F(P2a, P2b, P2q);
            if (c + 6 < NCH) LOAD_CHUNK_F(P2a, P2b, P2q, c + 6);
            PROC_F(P3a, P3b, P3q);
        }
    } else {
        // -------- backward: t = 511..256 --------
        Ba = La_v = Bb = Lb_v = 0.0f;
        B64 = (lane == 31) ? 1.0f : 0.0f;
        corr = (lane == 31) ? 0.0f : 1.0f;

        LOAD_CHUNK_B(P0a, P0b, P0q, 0);
        LOAD_CHUNK_B(P1a, P1b, P1q, 1);
        LOAD_CHUNK_B(P2a, P2b, P2q, 2);
        for (int c = 0; c < NCH; c += 4) {
            if (c + 3 < NCH) LOAD_CHUNK_B(P3a, P3b, P3q, c + 3);
            PROC_B(P0a, P0b, P0q);
            if (c + 4 < NCH) LOAD_CHUNK_B(P0a, P0b, P0q, c + 4);
            PROC_B(P1a, P1b, P1q);
            if (c + 5 < NCH) LOAD_CHUNK_B(P1a, P1b, P1q, c + 5);
            PROC_B(P2a, P2b, P2q);
            if (c + 6 < NCH) LOAD_CHUNK_B(P2a, P2b, P2q, c + 6);
            PROC_B(P3a, P3b, P3q);
        }

        // Publish B_{256}(s) = beta(s) + beta(s+1) + skip(s+2)*beta(s+2)
        {
            float _nb = __shfl_down_sync(FULL, Ba, 1);
            float _nl = __shfl_down_sync(FULL, La_v, 1);
            _nb = (lane == 31) ? B64 : _nb * corr;
            _nl = (lane == 31) ? 0.0f : _nl * corr;
            sBv[lane][0] = Ba + La_v;                  // B at s=4j
            sBv[lane][1] = La_v + Bb + sb * Lb_v;      // B at s=4j+1
            sBv[lane][2] = Bb + Lb_v;                  // B at s=4j+2
            sBv[lane][3] = Lb_v + _nb + saN * _nl;     // B at s=4j+3
            sBv[lane][4] = B64;                        // B at s=128
            sBo[lane] = off;
        }
    }

    __syncthreads();

    if (wid == 0) {
        // dot over this lane's states; true value = dot * 2^(offA+offB)
        float dot = Ba * sBv[lane][0] + La_v * sBv[lane][1]
                  + Bb * sBv[lane][2] + Lb_v * sBv[lane][3];
        if (lane == 31) dot += B64 * sBv[lane][4];
        int e = off + sBo[lane];

        int   ep;    // normalized exponent of lane contribution
        float m;     // mantissa in [1,2)
        if (dot > 0.0f) {
            int ie = ((__float_as_int(dot) >> 23) & 255) - 127;
            m  = dot * exp2i(-ie);
            ep = e + ie;
        } else {
            m  = 0.0f;
            ep = -0x40000000;
        }
        int emax = ep;
#pragma unroll
        for (int o = 16; o > 0; o >>= 1)
            emax = max(emax, __shfl_xor_sync(FULL, emax, o));
        float part = m * exp2i(ep - emax);
#pragma unroll
        for (int o = 16; o > 0; o >>= 1)
            part += __shfl_xor_sync(FULL, part, o);
        if (lane == 0)
            out[b] = -((__log2f(part) + (float)emax) * LN2F);
    }
}

extern "C" void kernel_launch(void* const* d_in, const int* in_sizes, int n_in,
                              void* d_out, int out_size)
{
    // Identify inputs by element count: y_true is B*L int32, y_pred is B*T*V f32
    const int* y_true = nullptr;
    const float* y_pred = nullptr;
    if (in_sizes[0] == B_ * L_) {
        y_true = (const int*)d_in[0];
        y_pred = (const float*)d_in[1];
    } else {
        y_true = (const int*)d_in[1];
        y_pred = (const float*)d_in[0];
    }
    float* out = (float*)d_out;

    // One 64-thread block per batch element: warp0 forward, warp1 backward
    ctc_forward_kernel<<<B_, 64>>>(y_true, y_pred, out);
}